// round 2
// baseline (speedup 1.0000x reference)
#include <cuda_runtime.h>
#include <math.h>

#define NTOK 1569
#define BATCH 8
#define CDIM 768
#define NHEAD 12
#define HDIM 64
#define BH (BATCH*NHEAD)            /* 96 */
#define BHND (BH*NTOK*HDIM)         /* 9639936 */
#define NBC (NTOK*BATCH*CDIM)       /* 9639936 */

// ---------------- scratch (device globals: no allocation allowed) ----------
__device__ float g_q[BHND];
__device__ float g_k[BHND];
__device__ float g_v[BHND];
__device__ float g_xs[BHND];
__device__ float g_t1[BHND];
__device__ float g_acc[BHND];
__device__ float g_rownorm[BATCH*NTOK];
__device__ float g_invtemp[BATCH];

// ---------------- per-token L2 norm over C (for inv_temp) ------------------
__global__ void rownorm_kernel(const float* __restrict__ x) {
    int r = (blockIdx.x * blockDim.x + threadIdx.x) >> 5;
    int lane = threadIdx.x & 31;
    if (r >= BATCH * NTOK) return;
    int b = r / NTOK, n = r - b * NTOK;
    const float* p = x + (size_t)n * (BATCH * CDIM) + b * CDIM;
    float ss = 0.f;
#pragma unroll
    for (int kblk = 0; kblk < 6; kblk++) {
        float4 v = *(const float4*)(p + kblk * 128 + lane * 4);
        ss += v.x * v.x + v.y * v.y + v.z * v.z + v.w * v.w;
    }
#pragma unroll
    for (int o = 16; o; o >>= 1) ss += __shfl_xor_sync(0xffffffffu, ss, o);
    if (lane == 0) g_rownorm[r] = sqrtf(ss);
}

__global__ void invtemp_kernel() {
    __shared__ float sh[256];
    int b = blockIdx.x;
    float s = 0.f;
    for (int n = threadIdx.x; n < NTOK; n += 256) s += g_rownorm[b * NTOK + n];
    sh[threadIdx.x] = s;
    __syncthreads();
    for (int o = 128; o; o >>= 1) {
        if (threadIdx.x < o) sh[threadIdx.x] += sh[threadIdx.x + o];
        __syncthreads();
    }
    if (threadIdx.x == 0) g_invtemp[b] = (sh[0] / (float)NTOK) * 0.125f;  // * hd^-0.5
}

// ---------------- qkv projection GEMM -------------------------------------
// q/k/v[b,h,n,d] = sum_c x[n,b,c] * Wqkv[t*768 + h*64 + d, c]
__global__ void qkv_gemm_kernel(const float* __restrict__ x, const float* __restrict__ W) {
    __shared__ float As[16][68];
    __shared__ float Bs[16][68];
    int tid = threadIdx.x;
    int txx = tid & 15, tyy = tid >> 4;
    int m0 = blockIdx.x * 64;
    int o0 = blockIdx.y * 64;
    int b = blockIdx.z;
    int rowL = tid >> 2;
    int cL = (tid & 3) << 2;

    float acc[4][4];
#pragma unroll
    for (int i = 0; i < 4; i++)
#pragma unroll
        for (int j = 0; j < 4; j++) acc[i][j] = 0.f;

    for (int c0 = 0; c0 < CDIM; c0 += 16) {
        float4 a4 = make_float4(0.f, 0.f, 0.f, 0.f);
        int gm = m0 + rowL;
        if (gm < NTOK)
            a4 = *(const float4*)(x + (size_t)gm * (BATCH * CDIM) + b * CDIM + c0 + cL);
        As[cL + 0][rowL] = a4.x; As[cL + 1][rowL] = a4.y;
        As[cL + 2][rowL] = a4.z; As[cL + 3][rowL] = a4.w;
        float4 b4 = *(const float4*)(W + (size_t)(o0 + rowL) * CDIM + c0 + cL);
        Bs[cL + 0][rowL] = b4.x; Bs[cL + 1][rowL] = b4.y;
        Bs[cL + 2][rowL] = b4.z; Bs[cL + 3][rowL] = b4.w;
        __syncthreads();
#pragma unroll
        for (int k = 0; k < 16; k++) {
            float4 av = *(const float4*)&As[k][tyy << 2];
            float4 bv = *(const float4*)&Bs[k][txx << 2];
            acc[0][0] += av.x * bv.x; acc[0][1] += av.x * bv.y; acc[0][2] += av.x * bv.z; acc[0][3] += av.x * bv.w;
            acc[1][0] += av.y * bv.x; acc[1][1] += av.y * bv.y; acc[1][2] += av.y * bv.z; acc[1][3] += av.y * bv.w;
            acc[2][0] += av.z * bv.x; acc[2][1] += av.z * bv.y; acc[2][2] += av.z * bv.z; acc[2][3] += av.z * bv.w;
            acc[3][0] += av.w * bv.x; acc[3][1] += av.w * bv.y; acc[3][2] += av.w * bv.z; acc[3][3] += av.w * bv.w;
        }
        __syncthreads();
    }

    int t = o0 / CDIM;
    int h = (o0 % CDIM) >> 6;  // 64-wide o-tile => single (t,h), d = 4*txx+j
    float* dst = (t == 0) ? g_q : ((t == 1) ? g_k : g_v);
    dst += (size_t)((b * NHEAD + h) * NTOK) * HDIM;
#pragma unroll
    for (int i = 0; i < 4; i++) {
        int n = m0 + (tyy << 2) + i;
        if (n < NTOK)
            *(float4*)&dst[(size_t)n * HDIM + (txx << 2)] =
                make_float4(acc[i][0], acc[i][1], acc[i][2], acc[i][3]);
    }
}

// ---------------- output projection GEMM -----------------------------------
// out[n,b,o] = prescale * sum_c src[b, c/64, n, c%64] * Wproj[o,c] + bias[o]
__global__ void proj_gemm_kernel(const float* __restrict__ src, const float* __restrict__ W,
                                 const float* __restrict__ bias, float* __restrict__ out,
                                 float prescale) {
    __shared__ float As[16][68];
    __shared__ float Bs[16][68];
    int tid = threadIdx.x;
    int txx = tid & 15, tyy = tid >> 4;
    int m0 = blockIdx.x * 64;
    int o0 = blockIdx.y * 64;
    int b = blockIdx.z;
    int rowL = tid >> 2;
    int cL = (tid & 3) << 2;

    float acc[4][4];
#pragma unroll
    for (int i = 0; i < 4; i++)
#pragma unroll
        for (int j = 0; j < 4; j++) acc[i][j] = 0.f;

    for (int c0 = 0; c0 < CDIM; c0 += 16) {
        int h = c0 >> 6;
        int dlo = c0 & 63;
        float4 a4 = make_float4(0.f, 0.f, 0.f, 0.f);
        int gm = m0 + rowL;
        if (gm < NTOK)
            a4 = *(const float4*)(src + (size_t)((b * NHEAD + h) * NTOK + gm) * HDIM + dlo + cL);
        As[cL + 0][rowL] = a4.x; As[cL + 1][rowL] = a4.y;
        As[cL + 2][rowL] = a4.z; As[cL + 3][rowL] = a4.w;
        float4 b4 = *(const float4*)(W + (size_t)(o0 + rowL) * CDIM + c0 + cL);
        Bs[cL + 0][rowL] = b4.x; Bs[cL + 1][rowL] = b4.y;
        Bs[cL + 2][rowL] = b4.z; Bs[cL + 3][rowL] = b4.w;
        __syncthreads();
#pragma unroll
        for (int k = 0; k < 16; k++) {
            float4 av = *(const float4*)&As[k][tyy << 2];
            float4 bv = *(const float4*)&Bs[k][txx << 2];
            acc[0][0] += av.x * bv.x; acc[0][1] += av.x * bv.y; acc[0][2] += av.x * bv.z; acc[0][3] += av.x * bv.w;
            acc[1][0] += av.y * bv.x; acc[1][1] += av.y * bv.y; acc[1][2] += av.y * bv.z; acc[1][3] += av.y * bv.w;
            acc[2][0] += av.z * bv.x; acc[2][1] += av.z * bv.y; acc[2][2] += av.z * bv.z; acc[2][3] += av.z * bv.w;
            acc[3][0] += av.w * bv.x; acc[3][1] += av.w * bv.y; acc[3][2] += av.w * bv.z; acc[3][3] += av.w * bv.w;
        }
        __syncthreads();
    }

    float4 bb = *(const float4*)(bias + o0 + (txx << 2));
#pragma unroll
    for (int i = 0; i < 4; i++) {
        int n = m0 + (tyy << 2) + i;
        if (n < NTOK) {
            float* po = out + (size_t)n * (BATCH * CDIM) + b * CDIM + o0 + (txx << 2);
            *(float4*)po = make_float4(acc[i][0] * prescale + bb.x,
                                       acc[i][1] * prescale + bb.y,
                                       acc[i][2] * prescale + bb.z,
                                       acc[i][3] * prescale + bb.w);
        }
    }
}

// ---------------- l2 normalize last dim (hd=64) ----------------------------
__global__ void l2norm_kernel(const float* __restrict__ in, float* __restrict__ out) {
    int r = (blockIdx.x * blockDim.x + threadIdx.x) >> 5;
    int lane = threadIdx.x & 31;
    if (r >= BH * NTOK) return;
    float2 v = *(const float2*)(in + (size_t)r * HDIM + lane * 2);
    float ss = v.x * v.x + v.y * v.y;
#pragma unroll
    for (int o = 16; o; o >>= 1) ss += __shfl_xor_sync(0xffffffffu, ss, o);
    float inv = 1.f / fmaxf(sqrtf(ss), 1e-12f);
    *(float2*)(out + (size_t)r * HDIM + lane * 2) = make_float2(v.x * inv, v.y * inv);
}

// ---------------- elementwise accumulate -----------------------------------
__global__ void add_kernel(float* __restrict__ a, const float* __restrict__ b) {
    int i = blockIdx.x * blockDim.x + threadIdx.x;
    if (i < BHND / 4) {
        float4 xa = ((float4*)a)[i];
        float4 xb = ((const float4*)b)[i];
        xa.x += xb.x; xa.y += xb.y; xa.z += xb.z; xa.w += xb.w;
        ((float4*)a)[i] = xa;
    }
}

// ---------------- flash attention (fp32 SIMT) ------------------------------
// O = softmax(Q K^T * scale) V over [B,H,N,hd], scale per batch or constant.
#define AT_SMEM_BYTES (4 * 64 * 68 * 4)

__global__ __launch_bounds__(128) void attn_kernel(
    const float* __restrict__ Q, const float* __restrict__ K,
    const float* __restrict__ V, float* __restrict__ O,
    int useInvTemp, float cscale) {
    extern __shared__ float sm[];
    float(*Qs)[68] = (float(*)[68])sm;
    float(*Kt)[68] = (float(*)[68])(sm + 64 * 68);
    float(*Vs)[68] = (float(*)[68])(sm + 2 * 64 * 68);
    float(*Ps)[68] = (float(*)[68])(sm + 3 * 64 * 68);

    int tid = threadIdx.x;
    int tx = tid & 15, ty = tid >> 4;  // ty in [0,8): rows 8*ty+i; cols 4*tx+j
    int bh = blockIdx.y;
    int m0 = blockIdx.x * 64;
    float scale = useInvTemp ? g_invtemp[bh / NHEAD] : cscale;
    const size_t base = (size_t)bh * NTOK * HDIM;

#pragma unroll
    for (int e = 0; e < 8; e++) {
        int idx = tid + e * 128;
        int row = idx >> 4;
        int dv = (idx & 15) << 2;
        float4 qv = make_float4(0.f, 0.f, 0.f, 0.f);
        if (m0 + row < NTOK)
            qv = *(const float4*)(Q + base + (size_t)(m0 + row) * HDIM + dv);
        *(float4*)&Qs[row][dv] = qv;
    }

    float acc[8][4];
    float m_i[8], l_i[8];
#pragma unroll
    for (int i = 0; i < 8; i++) {
        m_i[i] = -1e30f;
        l_i[i] = 0.f;
#pragma unroll
        for (int j = 0; j < 4; j++) acc[i][j] = 0.f;
    }

    for (int kt0 = 0; kt0 < NTOK; kt0 += 64) {
        __syncthreads();
#pragma unroll
        for (int e = 0; e < 8; e++) {
            int idx = tid + e * 128;
            int key = idx >> 4;
            int dv = (idx & 15) << 2;
            int gk = kt0 + key;
            float4 kv = make_float4(0.f, 0.f, 0.f, 0.f);
            float4 vv = make_float4(0.f, 0.f, 0.f, 0.f);
            if (gk < NTOK) {
                kv = *(const float4*)(K + base + (size_t)gk * HDIM + dv);
                vv = *(const float4*)(V + base + (size_t)gk * HDIM + dv);
            }
            Kt[dv + 0][key] = kv.x; Kt[dv + 1][key] = kv.y;
            Kt[dv + 2][key] = kv.z; Kt[dv + 3][key] = kv.w;
            *(float4*)&Vs[key][dv] = vv;
        }
        __syncthreads();

        float s[8][4];
#pragma unroll
        for (int i = 0; i < 8; i++)
#pragma unroll
            for (int j = 0; j < 4; j++) s[i][j] = 0.f;

#pragma unroll 4
        for (int kk = 0; kk < 64; kk++) {
            float4 bv = *(const float4*)&Kt[kk][tx << 2];
#pragma unroll
            for (int i = 0; i < 8; i++) {
                float a = Qs[(ty << 3) + i][kk];
                s[i][0] += a * bv.x; s[i][1] += a * bv.y;
                s[i][2] += a * bv.z; s[i][3] += a * bv.w;
            }
        }

        bool tail = (kt0 + 64 > NTOK);
#pragma unroll
        for (int i = 0; i < 8; i++) {
            float rmax = -1e30f;
#pragma unroll
            for (int j = 0; j < 4; j++) {
                s[i][j] *= scale;
                if (tail && kt0 + (tx << 2) + j >= NTOK) s[i][j] = -1e30f;
                rmax = fmaxf(rmax, s[i][j]);
            }
#pragma unroll
            for (int o = 8; o; o >>= 1)
                rmax = fmaxf(rmax, __shfl_xor_sync(0xffffffffu, rmax, o));
            float mnew = fmaxf(m_i[i], rmax);
            float alpha = __expf(m_i[i] - mnew);
            m_i[i] = mnew;
            float rs = 0.f;
#pragma unroll
            for (int j = 0; j < 4; j++) {
                s[i][j] = __expf(s[i][j] - mnew);
                rs += s[i][j];
            }
#pragma unroll
            for (int o = 8; o; o >>= 1) rs += __shfl_xor_sync(0xffffffffu, rs, o);
            l_i[i] = l_i[i] * alpha + rs;
            acc[i][0] *= alpha; acc[i][1] *= alpha;
            acc[i][2] *= alpha; acc[i][3] *= alpha;
            *(float4*)&Ps[(ty << 3) + i][tx << 2] =
                make_float4(s[i][0], s[i][1], s[i][2], s[i][3]);
        }
        __syncthreads();

#pragma unroll 4
        for (int kk = 0; kk < 64; kk++) {
            float4 bv = *(const float4*)&Vs[kk][tx << 2];
#pragma unroll
            for (int i = 0; i < 8; i++) {
                float a = Ps[(ty << 3) + i][kk];
                acc[i][0] += a * bv.x; acc[i][1] += a * bv.y;
                acc[i][2] += a * bv.z; acc[i][3] += a * bv.w;
            }
        }
    }

#pragma unroll
    for (int i = 0; i < 8; i++) {
        int n = m0 + (ty << 3) + i;
        if (n < NTOK) {
            float inv = 1.f / l_i[i];
            *(float4*)(O + base + (size_t)n * HDIM + (tx << 2)) =
                make_float4(acc[i][0] * inv, acc[i][1] * inv,
                            acc[i][2] * inv, acc[i][3] * inv);
        }
    }
}

// ---------------- host orchestration ---------------------------------------
extern "C" void kernel_launch(void* const* d_in, const int* in_sizes, int n_in,
                              void* d_out, int out_size) {
    const float* x = (const float*)d_in[0];
    const float* Wqkv = (const float*)d_in[1];
    const float* Wproj = (const float*)d_in[2];
    const float* bproj = (const float*)d_in[3];
    float* out = (float*)d_out;

    cudaFuncSetAttribute(attn_kernel, cudaFuncAttributeMaxDynamicSharedMemorySize,
                         AT_SMEM_BYTES);

    float *q, *k, *v, *xs, *t1, *accb;
    cudaGetSymbolAddress((void**)&q, g_q);
    cudaGetSymbolAddress((void**)&k, g_k);
    cudaGetSymbolAddress((void**)&v, g_v);
    cudaGetSymbolAddress((void**)&xs, g_xs);
    cudaGetSymbolAddress((void**)&t1, g_t1);
    cudaGetSymbolAddress((void**)&accb, g_acc);

    const int LN_GRID = (BH * NTOK * 32 + 255) / 256;
    const int ADD_GRID = (BHND / 4 + 255) / 256;
    dim3 ga((NTOK + 63) / 64, BH);         // 25 x 96
    dim3 gq((NTOK + 63) / 64, 36, BATCH);  // qkv gemm
    dim3 gp((NTOK + 63) / 64, 12, BATCH);  // proj gemm

    // inv_temp
    rownorm_kernel<<<(BATCH * NTOK * 32 + 255) / 256, 256>>>(x);
    invtemp_kernel<<<BATCH, 256>>>();

    // qkv projection
    qkv_gemm_kernel<<<gq, 256>>>(x, Wqkv);

    // original attention -> x_ori (second half of output)
    attn_kernel<<<ga, 128, AT_SMEM_BYTES>>>(q, k, v, t1, 0, 0.125f);
    proj_gemm_kernel<<<gp, 256>>>(t1, Wproj, bproj, out + NBC, 1.0f);

    // branch(v): writes accumulator directly
    l2norm_kernel<<<LN_GRID, 256>>>(v, xs);
    attn_kernel<<<ga, 128, AT_SMEM_BYTES>>>(xs, xs, xs, t1, 1, 0.f);
    l2norm_kernel<<<LN_GRID, 256>>>(t1, xs);
    attn_kernel<<<ga, 128, AT_SMEM_BYTES>>>(xs, xs, v, accb, 1, 0.f);

    // branch(k)
    l2norm_kernel<<<LN_GRID, 256>>>(k, xs);
    attn_kernel<<<ga, 128, AT_SMEM_BYTES>>>(xs, xs, xs, t1, 1, 0.f);
    l2norm_kernel<<<LN_GRID, 256>>>(t1, xs);
    attn_kernel<<<ga, 128, AT_SMEM_BYTES>>>(xs, xs, v, t1, 1, 0.f);
    add_kernel<<<ADD_GRID, 256>>>(accb, t1);

    // branch(q)
    l2norm_kernel<<<LN_GRID, 256>>>(q, xs);
    attn_kernel<<<ga, 128, AT_SMEM_BYTES>>>(xs, xs, xs, t1, 1, 0.f);
    l2norm_kernel<<<LN_GRID, 256>>>(t1, xs);
    attn_kernel<<<ga, 128, AT_SMEM_BYTES>>>(xs, xs, v, t1, 1, 0.f);
    add_kernel<<<ADD_GRID, 256>>>(accb, t1);

    // x_out = (sum/3) @ Wproj^T + bproj  (first half of output)
    proj_gemm_kernel<<<gp, 256>>>(accb, Wproj, bproj, out, 1.0f / 3.0f);
}

// round 4
// speedup vs baseline: 2.5185x; 2.5185x over previous
#include <cuda_runtime.h>
#include <math.h>
#include <stdint.h>

#define NTOK 1569
#define BATCH 8
#define CDIM 768
#define NHEAD 12
#define HDIM 64
#define BH (BATCH*NHEAD)            /* 96 */
#define BHND (BH*NTOK*HDIM)         /* 9639936 */
#define NBC (NTOK*BATCH*CDIM)       /* 9639936 */

// ---------------- scratch (device globals: no allocation allowed) ----------
__device__ float g_q[BHND];
__device__ float g_k[BHND];
__device__ float g_v[BHND];
__device__ float g_xs[BHND];
__device__ float g_t1[BHND];
__device__ float g_acc[BHND];
__device__ float g_rownorm[BATCH*NTOK];
__device__ float g_invtemp[BATCH];

// ---------------- tf32 helpers ---------------------------------------------
__device__ __forceinline__ float to_tf32(float x) {
    uint32_t u;
    asm("cvt.rna.tf32.f32 %0, %1;" : "=r"(u) : "f"(x));
    return __uint_as_float(u);
}

__device__ __forceinline__ void mma8(float* c, uint32_t a0, uint32_t a1,
                                     uint32_t a2, uint32_t a3,
                                     uint32_t b0, uint32_t b1) {
    asm volatile(
        "mma.sync.aligned.m16n8k8.row.col.f32.tf32.tf32.f32 "
        "{%0,%1,%2,%3}, {%4,%5,%6,%7}, {%8,%9}, {%0,%1,%2,%3};"
        : "+f"(c[0]), "+f"(c[1]), "+f"(c[2]), "+f"(c[3])
        : "r"(a0), "r"(a1), "r"(a2), "r"(a3), "r"(b0), "r"(b1));
}

// ---------------- per-token L2 norm over C (for inv_temp) ------------------
__global__ void rownorm_kernel(const float* __restrict__ x) {
    int r = (blockIdx.x * blockDim.x + threadIdx.x) >> 5;
    int lane = threadIdx.x & 31;
    if (r >= BATCH * NTOK) return;
    int b = r / NTOK, n = r - b * NTOK;
    const float* p = x + (size_t)n * (BATCH * CDIM) + b * CDIM;
    float ss = 0.f;
#pragma unroll
    for (int kblk = 0; kblk < 6; kblk++) {
        float4 v = *(const float4*)(p + kblk * 128 + lane * 4);
        ss += v.x * v.x + v.y * v.y + v.z * v.z + v.w * v.w;
    }
#pragma unroll
    for (int o = 16; o; o >>= 1) ss += __shfl_xor_sync(0xffffffffu, ss, o);
    if (lane == 0) g_rownorm[r] = sqrtf(ss);
}

__global__ void invtemp_kernel() {
    __shared__ float sh[256];
    int b = blockIdx.x;
    float s = 0.f;
    for (int n = threadIdx.x; n < NTOK; n += 256) s += g_rownorm[b * NTOK + n];
    sh[threadIdx.x] = s;
    __syncthreads();
    for (int o = 128; o; o >>= 1) {
        if (threadIdx.x < o) sh[threadIdx.x] += sh[threadIdx.x + o];
        __syncthreads();
    }
    if (threadIdx.x == 0) g_invtemp[b] = (sh[0] / (float)NTOK) * 0.125f;
}

// ---------------- l2 normalize last dim (hd=64) ----------------------------
__global__ void l2norm_kernel(const float* __restrict__ in, float* __restrict__ out) {
    int r = (blockIdx.x * blockDim.x + threadIdx.x) >> 5;
    int lane = threadIdx.x & 31;
    if (r >= BH * NTOK) return;
    float2 v = *(const float2*)(in + (size_t)r * HDIM + lane * 2);
    float ss = v.x * v.x + v.y * v.y;
#pragma unroll
    for (int o = 16; o; o >>= 1) ss += __shfl_xor_sync(0xffffffffu, ss, o);
    float inv = 1.f / fmaxf(sqrtf(ss), 1e-12f);
    *(float2*)(out + (size_t)r * HDIM + lane * 2) = make_float2(v.x * inv, v.y * inv);
}

// ---------------- elementwise accumulate -----------------------------------
__global__ void add_kernel(float* __restrict__ a, const float* __restrict__ b) {
    int i = blockIdx.x * blockDim.x + threadIdx.x;
    if (i < BHND / 4) {
        float4 xa = ((float4*)a)[i];
        float4 xb = ((const float4*)b)[i];
        xa.x += xb.x; xa.y += xb.y; xa.z += xb.z; xa.w += xb.w;
        ((float4*)a)[i] = xa;
    }
}

// ---------------- flash attention (tf32 tensor-core) ------------------------
// Block: 128 thr (4 warps). Q-tile 64 rows (16/warp), key blocks of 64.
#define AST 72
#define ATT_SMEM (4 * 64 * AST * 4)

__global__ __launch_bounds__(128) void attn_tc(
    const float* __restrict__ Q, const float* __restrict__ K,
    const float* __restrict__ V, float* __restrict__ O,
    int useInvTemp, float cscale) {
    extern __shared__ float sm[];
    float* Qs = sm;
    float* Ks = sm + 64 * AST;
    float* Vs = sm + 2 * 64 * AST;
    float* Ps = sm + 3 * 64 * AST;

    int tid = threadIdx.x;
    int warp = tid >> 5, lane = tid & 31;
    int g = lane >> 2, t = lane & 3;
    int bh = blockIdx.y;
    int m0 = blockIdx.x * 64;
    float scale = useInvTemp ? g_invtemp[bh / NHEAD] : cscale;
    const size_t base = (size_t)bh * NTOK * HDIM;

    // load Q tile (converted to tf32)
#pragma unroll
    for (int e = 0; e < 8; e++) {
        int idx = tid + e * 128;
        int row = idx >> 4;
        int d = (idx & 15) << 2;
        float4 qv = make_float4(0.f, 0.f, 0.f, 0.f);
        if (m0 + row < NTOK)
            qv = *(const float4*)(Q + base + (size_t)(m0 + row) * HDIM + d);
        Qs[row * AST + d + 0] = to_tf32(qv.x);
        Qs[row * AST + d + 1] = to_tf32(qv.y);
        Qs[row * AST + d + 2] = to_tf32(qv.z);
        Qs[row * AST + d + 3] = to_tf32(qv.w);
    }

    const int r0 = warp * 16 + g;  // this thread's rows: r0, r0+8

    float mA = -1e30f, mB = -1e30f, lA = 0.f, lB = 0.f;
    float o[8][4];
#pragma unroll
    for (int nt = 0; nt < 8; nt++)
#pragma unroll
        for (int j = 0; j < 4; j++) o[nt][j] = 0.f;

    for (int kt0 = 0; kt0 < NTOK; kt0 += 64) {
        __syncthreads();
#pragma unroll
        for (int e = 0; e < 8; e++) {
            int idx = tid + e * 128;
            int row = idx >> 4;
            int d = (idx & 15) << 2;
            float4 kv = make_float4(0.f, 0.f, 0.f, 0.f);
            float4 vv = make_float4(0.f, 0.f, 0.f, 0.f);
            if (kt0 + row < NTOK) {
                kv = *(const float4*)(K + base + (size_t)(kt0 + row) * HDIM + d);
                vv = *(const float4*)(V + base + (size_t)(kt0 + row) * HDIM + d);
            }
            Ks[row * AST + d + 0] = to_tf32(kv.x);
            Ks[row * AST + d + 1] = to_tf32(kv.y);
            Ks[row * AST + d + 2] = to_tf32(kv.z);
            Ks[row * AST + d + 3] = to_tf32(kv.w);
            Vs[row * AST + d + 0] = to_tf32(vv.x);
            Vs[row * AST + d + 1] = to_tf32(vv.y);
            Vs[row * AST + d + 2] = to_tf32(vv.z);
            Vs[row * AST + d + 3] = to_tf32(vv.w);
        }
        __syncthreads();

        // S = Q K^T  (per-warp 16x64)
        float s[8][4];
#pragma unroll
        for (int nt = 0; nt < 8; nt++)
#pragma unroll
            for (int j = 0; j < 4; j++) s[nt][j] = 0.f;

        const uint32_t* qu = (const uint32_t*)Qs;
        const uint32_t* ku = (const uint32_t*)Ks;
#pragma unroll
        for (int kt = 0; kt < 8; kt++) {
            uint32_t a0 = qu[r0 * AST + kt * 8 + t];
            uint32_t a1 = qu[(r0 + 8) * AST + kt * 8 + t];
            uint32_t a2 = qu[r0 * AST + kt * 8 + t + 4];
            uint32_t a3 = qu[(r0 + 8) * AST + kt * 8 + t + 4];
#pragma unroll
            for (int nt = 0; nt < 8; nt++) {
                uint32_t b0 = ku[(nt * 8 + g) * AST + kt * 8 + t];
                uint32_t b1 = ku[(nt * 8 + g) * AST + kt * 8 + t + 4];
                mma8(s[nt], a0, a1, a2, a3, b0, b1);
            }
        }

        // scale + tail mask
        bool tail = (kt0 + 64 > NTOK);
#pragma unroll
        for (int nt = 0; nt < 8; nt++) {
            s[nt][0] *= scale; s[nt][1] *= scale;
            s[nt][2] *= scale; s[nt][3] *= scale;
            if (tail) {
                int cg = kt0 + nt * 8 + 2 * t;
                if (cg >= NTOK)     { s[nt][0] = -1e30f; s[nt][2] = -1e30f; }
                if (cg + 1 >= NTOK) { s[nt][1] = -1e30f; s[nt][3] = -1e30f; }
            }
        }

        // online softmax (rows r0 -> A, r0+8 -> B)
        float rmA = -1e30f, rmB = -1e30f;
#pragma unroll
        for (int nt = 0; nt < 8; nt++) {
            rmA = fmaxf(rmA, fmaxf(s[nt][0], s[nt][1]));
            rmB = fmaxf(rmB, fmaxf(s[nt][2], s[nt][3]));
        }
        rmA = fmaxf(rmA, __shfl_xor_sync(0xffffffffu, rmA, 1));
        rmA = fmaxf(rmA, __shfl_xor_sync(0xffffffffu, rmA, 2));
        rmB = fmaxf(rmB, __shfl_xor_sync(0xffffffffu, rmB, 1));
        rmB = fmaxf(rmB, __shfl_xor_sync(0xffffffffu, rmB, 2));
        float mnA = fmaxf(mA, rmA), mnB = fmaxf(mB, rmB);
        float aA = __expf(mA - mnA), aB = __expf(mB - mnB);
        mA = mnA; mB = mnB;

        float rsA = 0.f, rsB = 0.f;
#pragma unroll
        for (int nt = 0; nt < 8; nt++) {
            float p0 = __expf(s[nt][0] - mnA);
            float p1 = __expf(s[nt][1] - mnA);
            float p2 = __expf(s[nt][2] - mnB);
            float p3 = __expf(s[nt][3] - mnB);
            rsA += p0 + p1; rsB += p2 + p3;
            int col = nt * 8 + 2 * t;
            Ps[r0 * AST + col]           = to_tf32(p0);
            Ps[r0 * AST + col + 1]       = to_tf32(p1);
            Ps[(r0 + 8) * AST + col]     = to_tf32(p2);
            Ps[(r0 + 8) * AST + col + 1] = to_tf32(p3);
        }
        rsA += __shfl_xor_sync(0xffffffffu, rsA, 1);
        rsA += __shfl_xor_sync(0xffffffffu, rsA, 2);
        rsB += __shfl_xor_sync(0xffffffffu, rsB, 1);
        rsB += __shfl_xor_sync(0xffffffffu, rsB, 2);
        lA = lA * aA + rsA;
        lB = lB * aB + rsB;
#pragma unroll
        for (int nt = 0; nt < 8; nt++) {
            o[nt][0] *= aA; o[nt][1] *= aA;
            o[nt][2] *= aB; o[nt][3] *= aB;
        }
        __syncwarp();

        // O += P V
        const uint32_t* pu = (const uint32_t*)Ps;
        const uint32_t* vu = (const uint32_t*)Vs;
#pragma unroll
        for (int kt = 0; kt < 8; kt++) {
            uint32_t a0 = pu[r0 * AST + kt * 8 + t];
            uint32_t a1 = pu[(r0 + 8) * AST + kt * 8 + t];
            uint32_t a2 = pu[r0 * AST + kt * 8 + t + 4];
            uint32_t a3 = pu[(r0 + 8) * AST + kt * 8 + t + 4];
#pragma unroll
            for (int nt = 0; nt < 8; nt++) {
                uint32_t b0 = vu[(kt * 8 + t) * AST + nt * 8 + g];
                uint32_t b1 = vu[(kt * 8 + t + 4) * AST + nt * 8 + g];
                mma8(o[nt], a0, a1, a2, a3, b0, b1);
            }
        }
    }

    float invA = 1.f / lA, invB = 1.f / lB;
    int gr0 = m0 + r0, gr1 = m0 + r0 + 8;
#pragma unroll
    for (int nt = 0; nt < 8; nt++) {
        int col = nt * 8 + 2 * t;
        if (gr0 < NTOK)
            *(float2*)(O + base + (size_t)gr0 * HDIM + col) =
                make_float2(o[nt][0] * invA, o[nt][1] * invA);
        if (gr1 < NTOK)
            *(float2*)(O + base + (size_t)gr1 * HDIM + col) =
                make_float2(o[nt][2] * invB, o[nt][3] * invB);
    }
}

// ---------------- qkv projection GEMM (tf32 tensor-core) --------------------
#define GST 36

__global__ __launch_bounds__(128) void qkv_tc(const float* __restrict__ x,
                                              const float* __restrict__ W) {
    __shared__ float As[64 * GST];
    __shared__ float Bs[64 * GST];
    int tid = threadIdx.x;
    int warp = tid >> 5, lane = tid & 31;
    int g = lane >> 2, t = lane & 3;
    int m0 = blockIdx.x * 64;
    int o0 = blockIdx.y * 64;
    int b = blockIdx.z;
    const int r0 = warp * 16 + g;

    float c[8][4];
#pragma unroll
    for (int nt = 0; nt < 8; nt++)
#pragma unroll
        for (int j = 0; j < 4; j++) c[nt][j] = 0.f;

    for (int c0 = 0; c0 < CDIM; c0 += 32) {
        __syncthreads();
#pragma unroll
        for (int e = 0; e < 4; e++) {
            int idx = tid + e * 128;
            int row = idx >> 3;
            int cs = (idx & 7) << 2;
            float4 a4 = make_float4(0.f, 0.f, 0.f, 0.f);
            if (m0 + row < NTOK)
                a4 = *(const float4*)(x + (size_t)(m0 + row) * (BATCH * CDIM) + b * CDIM + c0 + cs);
            As[row * GST + cs + 0] = to_tf32(a4.x);
            As[row * GST + cs + 1] = to_tf32(a4.y);
            As[row * GST + cs + 2] = to_tf32(a4.z);
            As[row * GST + cs + 3] = to_tf32(a4.w);
            float4 b4 = *(const float4*)(W + (size_t)(o0 + row) * CDIM + c0 + cs);
            Bs[row * GST + cs + 0] = to_tf32(b4.x);
            Bs[row * GST + cs + 1] = to_tf32(b4.y);
            Bs[row * GST + cs + 2] = to_tf32(b4.z);
            Bs[row * GST + cs + 3] = to_tf32(b4.w);
        }
        __syncthreads();

        const uint32_t* au = (const uint32_t*)As;
        const uint32_t* bu = (const uint32_t*)Bs;
#pragma unroll
        for (int kt = 0; kt < 4; kt++) {
            uint32_t a0 = au[r0 * GST + kt * 8 + t];
            uint32_t a1 = au[(r0 + 8) * GST + kt * 8 + t];
            uint32_t a2 = au[r0 * GST + kt * 8 + t + 4];
            uint32_t a3 = au[(r0 + 8) * GST + kt * 8 + t + 4];
#pragma unroll
            for (int nt = 0; nt < 8; nt++) {
                uint32_t b0 = bu[(nt * 8 + g) * GST + kt * 8 + t];
                uint32_t b1 = bu[(nt * 8 + g) * GST + kt * 8 + t + 4];
                mma8(c[nt], a0, a1, a2, a3, b0, b1);
            }
        }
    }

    int tsel = o0 / CDIM;
    int h = (o0 % CDIM) >> 6;
    float* dst = (tsel == 0) ? g_q : ((tsel == 1) ? g_k : g_v);
    dst += (size_t)((b * NHEAD + h) * NTOK) * HDIM;
    int gr0 = m0 + r0, gr1 = m0 + r0 + 8;
#pragma unroll
    for (int nt = 0; nt < 8; nt++) {
        int col = nt * 8 + 2 * t;
        if (gr0 < NTOK)
            *(float2*)&dst[(size_t)gr0 * HDIM + col] = make_float2(c[nt][0], c[nt][1]);
        if (gr1 < NTOK)
            *(float2*)&dst[(size_t)gr1 * HDIM + col] = make_float2(c[nt][2], c[nt][3]);
    }
}

// ---------------- output projection GEMM (tf32 tensor-core) -----------------
__global__ __launch_bounds__(128) void proj_tc(const float* __restrict__ src,
                                               const float* __restrict__ W,
                                               const float* __restrict__ bias,
                                               float* __restrict__ out,
                                               float prescale) {
    __shared__ float As[64 * GST];
    __shared__ float Bs[64 * GST];
    int tid = threadIdx.x;
    int warp = tid >> 5, lane = tid & 31;
    int g = lane >> 2, t = lane & 3;
    int m0 = blockIdx.x * 64;
    int o0 = blockIdx.y * 64;
    int b = blockIdx.z;
    const int r0 = warp * 16 + g;

    float c[8][4];
#pragma unroll
    for (int nt = 0; nt < 8; nt++)
#pragma unroll
        for (int j = 0; j < 4; j++) c[nt][j] = 0.f;

    for (int c0 = 0; c0 < CDIM; c0 += 32) {
        int h = c0 >> 6;
        int dlo = c0 & 63;
        __syncthreads();
#pragma unroll
        for (int e = 0; e < 4; e++) {
            int idx = tid + e * 128;
            int row = idx >> 3;
            int cs = (idx & 7) << 2;
            float4 a4 = make_float4(0.f, 0.f, 0.f, 0.f);
            if (m0 + row < NTOK)
                a4 = *(const float4*)(src + (size_t)((b * NHEAD + h) * NTOK + m0 + row) * HDIM + dlo + cs);
            As[row * GST + cs + 0] = to_tf32(a4.x);
            As[row * GST + cs + 1] = to_tf32(a4.y);
            As[row * GST + cs + 2] = to_tf32(a4.z);
            As[row * GST + cs + 3] = to_tf32(a4.w);
            float4 b4 = *(const float4*)(W + (size_t)(o0 + row) * CDIM + c0 + cs);
            Bs[row * GST + cs + 0] = to_tf32(b4.x);
            Bs[row * GST + cs + 1] = to_tf32(b4.y);
            Bs[row * GST + cs + 2] = to_tf32(b4.z);
            Bs[row * GST + cs + 3] = to_tf32(b4.w);
        }
        __syncthreads();

        const uint32_t* au = (const uint32_t*)As;
        const uint32_t* bu = (const uint32_t*)Bs;
#pragma unroll
        for (int kt = 0; kt < 4; kt++) {
            uint32_t a0 = au[r0 * GST + kt * 8 + t];
            uint32_t a1 = au[(r0 + 8) * GST + kt * 8 + t];
            uint32_t a2 = au[r0 * GST + kt * 8 + t + 4];
            uint32_t a3 = au[(r0 + 8) * GST + kt * 8 + t + 4];
#pragma unroll
            for (int nt = 0; nt < 8; nt++) {
                uint32_t b0 = bu[(nt * 8 + g) * GST + kt * 8 + t];
                uint32_t b1 = bu[(nt * 8 + g) * GST + kt * 8 + t + 4];
                mma8(c[nt], a0, a1, a2, a3, b0, b1);
            }
        }
    }

    int gr0 = m0 + r0, gr1 = m0 + r0 + 8;
#pragma unroll
    for (int nt = 0; nt < 8; nt++) {
        int col = nt * 8 + 2 * t;
        float b0 = bias[o0 + col], b1 = bias[o0 + col + 1];
        if (gr0 < NTOK)
            *(float2*)(out + (size_t)gr0 * (BATCH * CDIM) + b * CDIM + o0 + col) =
                make_float2(c[nt][0] * prescale + b0, c[nt][1] * prescale + b1);
        if (gr1 < NTOK)
            *(float2*)(out + (size_t)gr1 * (BATCH * CDIM) + b * CDIM + o0 + col) =
                make_float2(c[nt][2] * prescale + b0, c[nt][3] * prescale + b1);
    }
}

// ---------------- host orchestration ---------------------------------------
extern "C" void kernel_launch(void* const* d_in, const int* in_sizes, int n_in,
                              void* d_out, int out_size) {
    const float* x = (const float*)d_in[0];
    const float* Wqkv = (const float*)d_in[1];
    const float* Wproj = (const float*)d_in[2];
    const float* bproj = (const float*)d_in[3];
    float* out = (float*)d_out;

    cudaFuncSetAttribute(attn_tc, cudaFuncAttributeMaxDynamicSharedMemorySize,
                         ATT_SMEM);

    float *q, *k, *v, *xs, *t1, *accb;
    cudaGetSymbolAddress((void**)&q, g_q);
    cudaGetSymbolAddress((void**)&k, g_k);
    cudaGetSymbolAddress((void**)&v, g_v);
    cudaGetSymbolAddress((void**)&xs, g_xs);
    cudaGetSymbolAddress((void**)&t1, g_t1);
    cudaGetSymbolAddress((void**)&accb, g_acc);

    const int LN_GRID = (BH * NTOK * 32 + 255) / 256;
    const int ADD_GRID = (BHND / 4 + 255) / 256;
    dim3 ga((NTOK + 63) / 64, BH);
    dim3 gq((NTOK + 63) / 64, 36, BATCH);
    dim3 gp((NTOK + 63) / 64, 12, BATCH);

    rownorm_kernel<<<(BATCH * NTOK * 32 + 255) / 256, 256>>>(x);
    invtemp_kernel<<<BATCH, 256>>>();

    qkv_tc<<<gq, 128>>>(x, Wqkv);

    // original attention -> x_ori (second half of output)
    attn_tc<<<ga, 128, ATT_SMEM>>>(q, k, v, t1, 0, 0.125f);
    proj_tc<<<gp, 128>>>(t1, Wproj, bproj, out + NBC, 1.0f);

    // branch(v)
    l2norm_kernel<<<LN_GRID, 256>>>(v, xs);
    attn_tc<<<ga, 128, ATT_SMEM>>>(xs, xs, xs, t1, 1, 0.f);
    l2norm_kernel<<<LN_GRID, 256>>>(t1, xs);
    attn_tc<<<ga, 128, ATT_SMEM>>>(xs, xs, v, accb, 1, 0.f);

    // branch(k)
    l2norm_kernel<<<LN_GRID, 256>>>(k, xs);
    attn_tc<<<ga, 128, ATT_SMEM>>>(xs, xs, xs, t1, 1, 0.f);
    l2norm_kernel<<<LN_GRID, 256>>>(t1, xs);
    attn_tc<<<ga, 128, ATT_SMEM>>>(xs, xs, v, t1, 1, 0.f);
    add_kernel<<<ADD_GRID, 256>>>(accb, t1);

    // branch(q)
    l2norm_kernel<<<LN_GRID, 256>>>(q, xs);
    attn_tc<<<ga, 128, ATT_SMEM>>>(xs, xs, xs, t1, 1, 0.f);
    l2norm_kernel<<<LN_GRID, 256>>>(t1, xs);
    attn_tc<<<ga, 128, ATT_SMEM>>>(xs, xs, v, t1, 1, 0.f);
    add_kernel<<<ADD_GRID, 256>>>(accb, t1);

    proj_tc<<<gp, 128>>>(accb, Wproj, bproj, out, 1.0f / 3.0f);
}

// round 5
// speedup vs baseline: 2.7593x; 1.0956x over previous
#include <cuda_runtime.h>
#include <math.h>
#include <stdint.h>

#define NTOK 1569
#define BATCH 8
#define CDIM 768
#define NHEAD 12
#define HDIM 64
#define BH (BATCH*NHEAD)            /* 96 */
#define BHND (BH*NTOK*HDIM)         /* 9639936 */
#define NBC (NTOK*BATCH*CDIM)       /* 9639936 */

// ---------------- scratch (device globals: no allocation allowed) ----------
__device__ float g_q[BHND];
__device__ float g_k[BHND];
__device__ float g_v[BHND];
__device__ float g_xs[BHND];
__device__ float g_t1[BHND];
__device__ float g_acc[BHND];
__device__ float g_rownorm[BATCH*NTOK];
__device__ float g_invtemp[BATCH];

// ---------------- tf32 helpers ---------------------------------------------
__device__ __forceinline__ float to_tf32(float x) {
    uint32_t u;
    asm("cvt.rna.tf32.f32 %0, %1;" : "=r"(u) : "f"(x));
    return __uint_as_float(u);
}

__device__ __forceinline__ float ex2(float x) {
    float r;
    asm("ex2.approx.f32 %0, %1;" : "=f"(r) : "f"(x));
    return r;
}

__device__ __forceinline__ void mma8(float* c, uint32_t a0, uint32_t a1,
                                     uint32_t a2, uint32_t a3,
                                     uint32_t b0, uint32_t b1) {
    asm volatile(
        "mma.sync.aligned.m16n8k8.row.col.f32.tf32.tf32.f32 "
        "{%0,%1,%2,%3}, {%4,%5,%6,%7}, {%8,%9}, {%0,%1,%2,%3};"
        : "+f"(c[0]), "+f"(c[1]), "+f"(c[2]), "+f"(c[3])
        : "r"(a0), "r"(a1), "r"(a2), "r"(a3), "r"(b0), "r"(b1));
}

// ---------------- per-token L2 norm over C (for inv_temp) ------------------
__global__ void rownorm_kernel(const float* __restrict__ x) {
    int r = (blockIdx.x * blockDim.x + threadIdx.x) >> 5;
    int lane = threadIdx.x & 31;
    if (r >= BATCH * NTOK) return;
    int b = r / NTOK, n = r - b * NTOK;
    const float* p = x + (size_t)n * (BATCH * CDIM) + b * CDIM;
    float ss = 0.f;
#pragma unroll
    for (int kblk = 0; kblk < 6; kblk++) {
        float4 v = *(const float4*)(p + kblk * 128 + lane * 4);
        ss += v.x * v.x + v.y * v.y + v.z * v.z + v.w * v.w;
    }
#pragma unroll
    for (int o = 16; o; o >>= 1) ss += __shfl_xor_sync(0xffffffffu, ss, o);
    if (lane == 0) g_rownorm[r] = sqrtf(ss);
}

__global__ void invtemp_kernel() {
    __shared__ float sh[256];
    int b = blockIdx.x;
    float s = 0.f;
    for (int n = threadIdx.x; n < NTOK; n += 256) s += g_rownorm[b * NTOK + n];
    sh[threadIdx.x] = s;
    __syncthreads();
    for (int o = 128; o; o >>= 1) {
        if (threadIdx.x < o) sh[threadIdx.x] += sh[threadIdx.x + o];
        __syncthreads();
    }
    if (threadIdx.x == 0) g_invtemp[b] = (sh[0] / (float)NTOK) * 0.125f;
}

// ---------------- l2 normalize last dim (hd=64) ----------------------------
__global__ void l2norm_kernel(const float* __restrict__ in, float* __restrict__ out) {
    int r = (blockIdx.x * blockDim.x + threadIdx.x) >> 5;
    int lane = threadIdx.x & 31;
    if (r >= BH * NTOK) return;
    float2 v = *(const float2*)(in + (size_t)r * HDIM + lane * 2);
    float ss = v.x * v.x + v.y * v.y;
#pragma unroll
    for (int o = 16; o; o >>= 1) ss += __shfl_xor_sync(0xffffffffu, ss, o);
    float inv = 1.f / fmaxf(sqrtf(ss), 1e-12f);
    *(float2*)(out + (size_t)r * HDIM + lane * 2) = make_float2(v.x * inv, v.y * inv);
}

// ---------------- elementwise accumulate -----------------------------------
__global__ void add_kernel(float* __restrict__ a, const float* __restrict__ b) {
    int i = blockIdx.x * blockDim.x + threadIdx.x;
    if (i < BHND / 4) {
        float4 xa = ((float4*)a)[i];
        float4 xb = ((const float4*)b)[i];
        xa.x += xb.x; xa.y += xb.y; xa.z += xb.z; xa.w += xb.w;
        ((float4*)a)[i] = xa;
    }
}

// ---------------- flash attention (tf32 tensor-core, no-max softmax) --------
// Block: 128 thr (4 warps). Q-tile 64 rows (16/warp), key blocks of 64.
// Smem stride 68 (== 4 mod 32): bank = 4g+t permutation, conflict-free.
// Ps aliases the Q staging buffer (Q lives in registers after prologue).
#define AST 68
#define ATT_SMEM (3 * 64 * AST * 4)

__global__ __launch_bounds__(128) void attn_tc(
    const float* __restrict__ Q, const float* __restrict__ K,
    const float* __restrict__ V, float* __restrict__ O,
    int useInvTemp, float cscale) {
    extern __shared__ float sm[];
    float* Ps = sm;                 // P buffer; also Q staging in prologue
    float* Ks = sm + 64 * AST;
    float* Vs = sm + 2 * 64 * AST;

    int tid = threadIdx.x;
    int warp = tid >> 5, lane = tid & 31;
    int g = lane >> 2, t = lane & 3;
    int bh = blockIdx.y;
    int m0 = blockIdx.x * 64;
    float scale = useInvTemp ? g_invtemp[bh / NHEAD] : cscale;
    const float qscale = scale * 1.4426950408889634f;  // fold log2(e) for ex2
    const size_t base = (size_t)bh * NTOK * HDIM;
    const int r0 = warp * 16 + g;   // this thread's rows: r0, r0+8

    // ---- stage Q (scaled, tf32) then hoist fragments into registers ----
#pragma unroll
    for (int e = 0; e < 8; e++) {
        int idx = tid + e * 128;
        int row = idx >> 4;
        int d = (idx & 15) << 2;
        float4 qv = make_float4(0.f, 0.f, 0.f, 0.f);
        if (m0 + row < NTOK)
            qv = *(const float4*)(Q + base + (size_t)(m0 + row) * HDIM + d);
        float4 w;
        w.x = to_tf32(qv.x * qscale); w.y = to_tf32(qv.y * qscale);
        w.z = to_tf32(qv.z * qscale); w.w = to_tf32(qv.w * qscale);
        *(float4*)&Ps[row * AST + d] = w;
    }
    __syncthreads();

    uint32_t qa[8][4];
    {
        const uint32_t* pu = (const uint32_t*)Ps;
#pragma unroll
        for (int kt = 0; kt < 8; kt++) {
            qa[kt][0] = pu[r0 * AST + kt * 8 + t];
            qa[kt][1] = pu[(r0 + 8) * AST + kt * 8 + t];
            qa[kt][2] = pu[r0 * AST + kt * 8 + t + 4];
            qa[kt][3] = pu[(r0 + 8) * AST + kt * 8 + t + 4];
        }
    }

    float lA = 0.f, lB = 0.f;
    float o[8][4];
#pragma unroll
    for (int nt = 0; nt < 8; nt++)
#pragma unroll
        for (int j = 0; j < 4; j++) o[nt][j] = 0.f;

    for (int kt0 = 0; kt0 < NTOK; kt0 += 64) {
        __syncthreads();
#pragma unroll
        for (int e = 0; e < 8; e++) {
            int idx = tid + e * 128;
            int row = idx >> 4;
            int d = (idx & 15) << 2;
            float4 kv = make_float4(0.f, 0.f, 0.f, 0.f);
            float4 vv = make_float4(0.f, 0.f, 0.f, 0.f);
            if (kt0 + row < NTOK) {
                kv = *(const float4*)(K + base + (size_t)(kt0 + row) * HDIM + d);
                vv = *(const float4*)(V + base + (size_t)(kt0 + row) * HDIM + d);
            }
            float4 kw, vw;
            kw.x = to_tf32(kv.x); kw.y = to_tf32(kv.y);
            kw.z = to_tf32(kv.z); kw.w = to_tf32(kv.w);
            vw.x = to_tf32(vv.x); vw.y = to_tf32(vv.y);
            vw.z = to_tf32(vv.z); vw.w = to_tf32(vv.w);
            *(float4*)&Ks[row * AST + d] = kw;
            *(float4*)&Vs[row * AST + d] = vw;
        }
        __syncthreads();

        // ---- S = (Q*qscale) K^T ----
        float s[8][4];
#pragma unroll
        for (int nt = 0; nt < 8; nt++)
#pragma unroll
            for (int j = 0; j < 4; j++) s[nt][j] = 0.f;

        const uint32_t* ku = (const uint32_t*)Ks;
#pragma unroll
        for (int kt = 0; kt < 8; kt++) {
#pragma unroll
            for (int nt = 0; nt < 8; nt++) {
                uint32_t b0 = ku[(nt * 8 + g) * AST + kt * 8 + t];
                uint32_t b1 = ku[(nt * 8 + g) * AST + kt * 8 + t + 4];
                mma8(s[nt], qa[kt][0], qa[kt][1], qa[kt][2], qa[kt][3], b0, b1);
            }
        }

        // ---- no-max softmax: p = 2^s (s already includes scale*log2e) ----
        bool tail = (kt0 + 64 > NTOK);
#pragma unroll
        for (int nt = 0; nt < 8; nt++) {
            if (tail) {
                int cg = kt0 + nt * 8 + 2 * t;
                if (cg >= NTOK)     { s[nt][0] = -1e30f; s[nt][2] = -1e30f; }
                if (cg + 1 >= NTOK) { s[nt][1] = -1e30f; s[nt][3] = -1e30f; }
            }
            float p0 = ex2(s[nt][0]);
            float p1 = ex2(s[nt][1]);
            float p2 = ex2(s[nt][2]);
            float p3 = ex2(s[nt][3]);
            lA += p0 + p1; lB += p2 + p3;
            int col = nt * 8 + 2 * t;
            *(float2*)&Ps[r0 * AST + col] =
                make_float2(to_tf32(p0), to_tf32(p1));
            *(float2*)&Ps[(r0 + 8) * AST + col] =
                make_float2(to_tf32(p2), to_tf32(p3));
        }
        __syncwarp();

        // ---- O += P V ----
        const uint32_t* pu = (const uint32_t*)Ps;
        const uint32_t* vu = (const uint32_t*)Vs;
#pragma unroll
        for (int kt = 0; kt < 8; kt++) {
            uint32_t a0 = pu[r0 * AST + kt * 8 + t];
            uint32_t a1 = pu[(r0 + 8) * AST + kt * 8 + t];
            uint32_t a2 = pu[r0 * AST + kt * 8 + t + 4];
            uint32_t a3 = pu[(r0 + 8) * AST + kt * 8 + t + 4];
#pragma unroll
            for (int nt = 0; nt < 8; nt++) {
                uint32_t b0 = vu[(kt * 8 + t) * AST + nt * 8 + g];
                uint32_t b1 = vu[(kt * 8 + t + 4) * AST + nt * 8 + g];
                mma8(o[nt], a0, a1, a2, a3, b0, b1);
            }
        }
    }

    // deferred l reduction over the 4 t-lanes of each row group
    lA += __shfl_xor_sync(0xffffffffu, lA, 1);
    lA += __shfl_xor_sync(0xffffffffu, lA, 2);
    lB += __shfl_xor_sync(0xffffffffu, lB, 1);
    lB += __shfl_xor_sync(0xffffffffu, lB, 2);
    float invA = 1.f / lA, invB = 1.f / lB;
    int gr0 = m0 + r0, gr1 = m0 + r0 + 8;
#pragma unroll
    for (int nt = 0; nt < 8; nt++) {
        int col = nt * 8 + 2 * t;
        if (gr0 < NTOK)
            *(float2*)(O + base + (size_t)gr0 * HDIM + col) =
                make_float2(o[nt][0] * invA, o[nt][1] * invA);
        if (gr1 < NTOK)
            *(float2*)(O + base + (size_t)gr1 * HDIM + col) =
                make_float2(o[nt][2] * invB, o[nt][3] * invB);
    }
}

// ---------------- qkv projection GEMM (tf32 tensor-core) --------------------
#define GST 36

__global__ __launch_bounds__(128) void qkv_tc(const float* __restrict__ x,
                                              const float* __restrict__ W) {
    __shared__ float As[64 * GST];
    __shared__ float Bs[64 * GST];
    int tid = threadIdx.x;
    int warp = tid >> 5, lane = tid & 31;
    int g = lane >> 2, t = lane & 3;
    int m0 = blockIdx.x * 64;
    int o0 = blockIdx.y * 64;
    int b = blockIdx.z;
    const int r0 = warp * 16 + g;

    float c[8][4];
#pragma unroll
    for (int nt = 0; nt < 8; nt++)
#pragma unroll
        for (int j = 0; j < 4; j++) c[nt][j] = 0.f;

    for (int c0 = 0; c0 < CDIM; c0 += 32) {
        __syncthreads();
#pragma unroll
        for (int e = 0; e < 4; e++) {
            int idx = tid + e * 128;
            int row = idx >> 3;
            int cs = (idx & 7) << 2;
            float4 a4 = make_float4(0.f, 0.f, 0.f, 0.f);
            if (m0 + row < NTOK)
                a4 = *(const float4*)(x + (size_t)(m0 + row) * (BATCH * CDIM) + b * CDIM + c0 + cs);
            float4 aw;
            aw.x = to_tf32(a4.x); aw.y = to_tf32(a4.y);
            aw.z = to_tf32(a4.z); aw.w = to_tf32(a4.w);
            *(float4*)&As[row * GST + cs] = aw;
            float4 b4 = *(const float4*)(W + (size_t)(o0 + row) * CDIM + c0 + cs);
            float4 bw;
            bw.x = to_tf32(b4.x); bw.y = to_tf32(b4.y);
            bw.z = to_tf32(b4.z); bw.w = to_tf32(b4.w);
            *(float4*)&Bs[row * GST + cs] = bw;
        }
        __syncthreads();

        const uint32_t* au = (const uint32_t*)As;
        const uint32_t* bu = (const uint32_t*)Bs;
#pragma unroll
        for (int kt = 0; kt < 4; kt++) {
            uint32_t a0 = au[r0 * GST + kt * 8 + t];
            uint32_t a1 = au[(r0 + 8) * GST + kt * 8 + t];
            uint32_t a2 = au[r0 * GST + kt * 8 + t + 4];
            uint32_t a3 = au[(r0 + 8) * GST + kt * 8 + t + 4];
#pragma unroll
            for (int nt = 0; nt < 8; nt++) {
                uint32_t b0 = bu[(nt * 8 + g) * GST + kt * 8 + t];
                uint32_t b1 = bu[(nt * 8 + g) * GST + kt * 8 + t + 4];
                mma8(c[nt], a0, a1, a2, a3, b0, b1);
            }
        }
    }

    int tsel = o0 / CDIM;
    int h = (o0 % CDIM) >> 6;
    float* dst = (tsel == 0) ? g_q : ((tsel == 1) ? g_k : g_v);
    dst += (size_t)((b * NHEAD + h) * NTOK) * HDIM;
    int gr0 = m0 + r0, gr1 = m0 + r0 + 8;
#pragma unroll
    for (int nt = 0; nt < 8; nt++) {
        int col = nt * 8 + 2 * t;
        if (gr0 < NTOK)
            *(float2*)&dst[(size_t)gr0 * HDIM + col] = make_float2(c[nt][0], c[nt][1]);
        if (gr1 < NTOK)
            *(float2*)&dst[(size_t)gr1 * HDIM + col] = make_float2(c[nt][2], c[nt][3]);
    }
}

// ---------------- output projection GEMM (tf32 tensor-core) -----------------
__global__ __launch_bounds__(128) void proj_tc(const float* __restrict__ src,
                                               const float* __restrict__ W,
                                               const float* __restrict__ bias,
                                               float* __restrict__ out,
                                               float prescale) {
    __shared__ float As[64 * GST];
    __shared__ float Bs[64 * GST];
    int tid = threadIdx.x;
    int warp = tid >> 5, lane = tid & 31;
    int g = lane >> 2, t = lane & 3;
    int m0 = blockIdx.x * 64;
    int o0 = blockIdx.y * 64;
    int b = blockIdx.z;
    const int r0 = warp * 16 + g;

    float c[8][4];
#pragma unroll
    for (int nt = 0; nt < 8; nt++)
#pragma unroll
        for (int j = 0; j < 4; j++) c[nt][j] = 0.f;

    for (int c0 = 0; c0 < CDIM; c0 += 32) {
        int h = c0 >> 6;
        int dlo = c0 & 63;
        __syncthreads();
#pragma unroll
        for (int e = 0; e < 4; e++) {
            int idx = tid + e * 128;
            int row = idx >> 3;
            int cs = (idx & 7) << 2;
            float4 a4 = make_float4(0.f, 0.f, 0.f, 0.f);
            if (m0 + row < NTOK)
                a4 = *(const float4*)(src + (size_t)((b * NHEAD + h) * NTOK + m0 + row) * HDIM + dlo + cs);
            float4 aw;
            aw.x = to_tf32(a4.x); aw.y = to_tf32(a4.y);
            aw.z = to_tf32(a4.z); aw.w = to_tf32(a4.w);
            *(float4*)&As[row * GST + cs] = aw;
            float4 b4 = *(const float4*)(W + (size_t)(o0 + row) * CDIM + c0 + cs);
            float4 bw;
            bw.x = to_tf32(b4.x); bw.y = to_tf32(b4.y);
            bw.z = to_tf32(b4.z); bw.w = to_tf32(b4.w);
            *(float4*)&Bs[row * GST + cs] = bw;
        }
        __syncthreads();

        const uint32_t* au = (const uint32_t*)As;
        const uint32_t* bu = (const uint32_t*)Bs;
#pragma unroll
        for (int kt = 0; kt < 4; kt++) {
            uint32_t a0 = au[r0 * GST + kt * 8 + t];
            uint32_t a1 = au[(r0 + 8) * GST + kt * 8 + t];
            uint32_t a2 = au[r0 * GST + kt * 8 + t + 4];
            uint32_t a3 = au[(r0 + 8) * GST + kt * 8 + t + 4];
#pragma unroll
            for (int nt = 0; nt < 8; nt++) {
                uint32_t b0 = bu[(nt * 8 + g) * GST + kt * 8 + t];
                uint32_t b1 = bu[(nt * 8 + g) * GST + kt * 8 + t + 4];
                mma8(c[nt], a0, a1, a2, a3, b0, b1);
            }
        }
    }

    int gr0 = m0 + r0, gr1 = m0 + r0 + 8;
#pragma unroll
    for (int nt = 0; nt < 8; nt++) {
        int col = nt * 8 + 2 * t;
        float b0 = bias[o0 + col], b1 = bias[o0 + col + 1];
        if (gr0 < NTOK)
            *(float2*)(out + (size_t)gr0 * (BATCH * CDIM) + b * CDIM + o0 + col) =
                make_float2(c[nt][0] * prescale + b0, c[nt][1] * prescale + b1);
        if (gr1 < NTOK)
            *(float2*)(out + (size_t)gr1 * (BATCH * CDIM) + b * CDIM + o0 + col) =
                make_float2(c[nt][2] * prescale + b0, c[nt][3] * prescale + b1);
    }
}

// ---------------- host orchestration ---------------------------------------
extern "C" void kernel_launch(void* const* d_in, const int* in_sizes, int n_in,
                              void* d_out, int out_size) {
    const float* x = (const float*)d_in[0];
    const float* Wqkv = (const float*)d_in[1];
    const float* Wproj = (const float*)d_in[2];
    const float* bproj = (const float*)d_in[3];
    float* out = (float*)d_out;

    cudaFuncSetAttribute(attn_tc, cudaFuncAttributeMaxDynamicSharedMemorySize,
                         ATT_SMEM);

    float *q, *k, *v, *xs, *t1, *accb;
    cudaGetSymbolAddress((void**)&q, g_q);
    cudaGetSymbolAddress((void**)&k, g_k);
    cudaGetSymbolAddress((void**)&v, g_v);
    cudaGetSymbolAddress((void**)&xs, g_xs);
    cudaGetSymbolAddress((void**)&t1, g_t1);
    cudaGetSymbolAddress((void**)&accb, g_acc);

    const int LN_GRID = (BH * NTOK * 32 + 255) / 256;
    const int ADD_GRID = (BHND / 4 + 255) / 256;
    dim3 ga((NTOK + 63) / 64, BH);
    dim3 gq((NTOK + 63) / 64, 36, BATCH);
    dim3 gp((NTOK + 63) / 64, 12, BATCH);

    rownorm_kernel<<<(BATCH * NTOK * 32 + 255) / 256, 256>>>(x);
    invtemp_kernel<<<BATCH, 256>>>();

    qkv_tc<<<gq, 128>>>(x, Wqkv);

    // original attention -> x_ori (second half of output)
    attn_tc<<<ga, 128, ATT_SMEM>>>(q, k, v, t1, 0, 0.125f);
    proj_tc<<<gp, 128>>>(t1, Wproj, bproj, out + NBC, 1.0f);

    // branch(v)
    l2norm_kernel<<<LN_GRID, 256>>>(v, xs);
    attn_tc<<<ga, 128, ATT_SMEM>>>(xs, xs, xs, t1, 1, 0.f);
    l2norm_kernel<<<LN_GRID, 256>>>(t1, xs);
    attn_tc<<<ga, 128, ATT_SMEM>>>(xs, xs, v, accb, 1, 0.f);

    // branch(k)
    l2norm_kernel<<<LN_GRID, 256>>>(k, xs);
    attn_tc<<<ga, 128, ATT_SMEM>>>(xs, xs, xs, t1, 1, 0.f);
    l2norm_kernel<<<LN_GRID, 256>>>(t1, xs);
    attn_tc<<<ga, 128, ATT_SMEM>>>(xs, xs, v, t1, 1, 0.f);
    add_kernel<<<ADD_GRID, 256>>>(accb, t1);

    // branch(q)
    l2norm_kernel<<<LN_GRID, 256>>>(q, xs);
    attn_tc<<<ga, 128, ATT_SMEM>>>(xs, xs, xs, t1, 1, 0.f);
    l2norm_kernel<<<LN_GRID, 256>>>(t1, xs);
    attn_tc<<<ga, 128, ATT_SMEM>>>(xs, xs, v, t1, 1, 0.f);
    add_kernel<<<ADD_GRID, 256>>>(accb, t1);

    proj_tc<<<gp, 128>>>(accb, Wproj, bproj, out, 1.0f / 3.0f);
}

// round 6
// speedup vs baseline: 3.4150x; 1.2376x over previous
#include <cuda_runtime.h>
#include <math.h>
#include <stdint.h>

#define NTOK 1569
#define BATCH 8
#define CDIM 768
#define NHEAD 12
#define HDIM 64
#define BH (BATCH*NHEAD)            /* 96 */
#define BHND (BH*NTOK*HDIM)         /* 9639936 */
#define NBC (NTOK*BATCH*CDIM)       /* 9639936 */

// ---------------- scratch (device globals: no allocation allowed) ----------
__device__ float g_q[BHND];
__device__ float g_k[BHND];
__device__ float g_v[BHND];
__device__ float g_xs[BHND];
__device__ float g_t1[BHND];
__device__ float g_acc[BHND];
__device__ float g_rownorm[BATCH*NTOK];
__device__ float g_invtemp[BATCH];

// ---------------- tf32 helpers ---------------------------------------------
__device__ __forceinline__ float to_tf32(float x) {
    uint32_t u;
    asm("cvt.rna.tf32.f32 %0, %1;" : "=r"(u) : "f"(x));
    return __uint_as_float(u);
}

__device__ __forceinline__ float ex2(float x) {
    float r;
    asm("ex2.approx.f32 %0, %1;" : "=f"(r) : "f"(x));
    return r;
}

__device__ __forceinline__ void mma8(float* c, uint32_t a0, uint32_t a1,
                                     uint32_t a2, uint32_t a3,
                                     uint32_t b0, uint32_t b1) {
    asm volatile(
        "mma.sync.aligned.m16n8k8.row.col.f32.tf32.tf32.f32 "
        "{%0,%1,%2,%3}, {%4,%5,%6,%7}, {%8,%9}, {%0,%1,%2,%3};"
        : "+f"(c[0]), "+f"(c[1]), "+f"(c[2]), "+f"(c[3])
        : "r"(a0), "r"(a1), "r"(a2), "r"(a3), "r"(b0), "r"(b1));
}

// ---------------- per-token L2 norm over C (for inv_temp) ------------------
__global__ void rownorm_kernel(const float* __restrict__ x) {
    int r = (blockIdx.x * blockDim.x + threadIdx.x) >> 5;
    int lane = threadIdx.x & 31;
    if (r >= BATCH * NTOK) return;
    int b = r / NTOK, n = r - b * NTOK;
    const float* p = x + (size_t)n * (BATCH * CDIM) + b * CDIM;
    float ss = 0.f;
#pragma unroll
    for (int kblk = 0; kblk < 6; kblk++) {
        float4 v = *(const float4*)(p + kblk * 128 + lane * 4);
        ss += v.x * v.x + v.y * v.y + v.z * v.z + v.w * v.w;
    }
#pragma unroll
    for (int o = 16; o; o >>= 1) ss += __shfl_xor_sync(0xffffffffu, ss, o);
    if (lane == 0) g_rownorm[r] = sqrtf(ss);
}

__global__ void invtemp_kernel() {
    __shared__ float sh[256];
    int b = blockIdx.x;
    float s = 0.f;
    for (int n = threadIdx.x; n < NTOK; n += 256) s += g_rownorm[b * NTOK + n];
    sh[threadIdx.x] = s;
    __syncthreads();
    for (int o = 128; o; o >>= 1) {
        if (threadIdx.x < o) sh[threadIdx.x] += sh[threadIdx.x + o];
        __syncthreads();
    }
    if (threadIdx.x == 0) g_invtemp[b] = (sh[0] / (float)NTOK) * 0.125f;
}

// ---------------- l2 normalize last dim (hd=64) ----------------------------
__global__ void l2norm_kernel(const float* __restrict__ in, float* __restrict__ out) {
    int r = (blockIdx.x * blockDim.x + threadIdx.x) >> 5;
    int lane = threadIdx.x & 31;
    if (r >= BH * NTOK) return;
    float2 v = *(const float2*)(in + (size_t)r * HDIM + lane * 2);
    float ss = v.x * v.x + v.y * v.y;
#pragma unroll
    for (int o = 16; o; o >>= 1) ss += __shfl_xor_sync(0xffffffffu, ss, o);
    float inv = 1.f / fmaxf(sqrtf(ss), 1e-12f);
    *(float2*)(out + (size_t)r * HDIM + lane * 2) = make_float2(v.x * inv, v.y * inv);
}

// ---------------- elementwise accumulate -----------------------------------
__global__ void add_kernel(float* __restrict__ a, const float* __restrict__ b) {
    int i = blockIdx.x * blockDim.x + threadIdx.x;
    if (i < BHND / 4) {
        float4 xa = ((float4*)a)[i];
        float4 xb = ((const float4*)b)[i];
        xa.x += xb.x; xa.y += xb.y; xa.z += xb.z; xa.w += xb.w;
        ((float4*)a)[i] = xa;
    }
}

// ---------------- flash attention (tf32 tensor-core, M=32/warp) -------------
// Block: 128 thr (4 warps). CTA Q-tile 128 rows; each warp owns 32 rows as
// two m16 blocks, sharing every K/V fragment between them (halves B traffic).
// Strides: Q/P/K = 68 (bank 4g+t perm), V = 72 (bank 8t+g perm) -> conflict-free.
#define AST 68
#define VST 72
#define ATT_SMEM ((128*AST + 64*AST + 64*VST) * 4)

__global__ __launch_bounds__(128) void attn_tc(
    const float* __restrict__ Q, const float* __restrict__ K,
    const float* __restrict__ V, float* __restrict__ O,
    int useInvTemp, float cscale) {
    extern __shared__ float sm[];
    float* Ps = sm;                       // 128 x AST: Q staging, then P
    float* Ks = sm + 128 * AST;           // 64 x AST
    float* Vs = sm + 128 * AST + 64 * AST;// 64 x VST

    int tid = threadIdx.x;
    int warp = tid >> 5, lane = tid & 31;
    int g = lane >> 2, t = lane & 3;
    int bh = blockIdx.y;
    int m0 = blockIdx.x * 128;
    float scale = useInvTemp ? g_invtemp[bh / NHEAD] : cscale;
    const float qscale = scale * 1.4426950408889634f;  // fold log2(e) for ex2
    const size_t base = (size_t)bh * NTOK * HDIM;
    const int rA = warp * 32 + g;        // block A rows: rA, rA+8
    const int rB = warp * 32 + 16 + g;   // block B rows: rB, rB+8

    // ---- stage Q (scaled, tf32) into Ps ----
#pragma unroll
    for (int e = 0; e < 16; e++) {
        int idx = tid + e * 128;
        int row = idx >> 4;
        int d = (idx & 15) << 2;
        float4 qv = make_float4(0.f, 0.f, 0.f, 0.f);
        if (m0 + row < NTOK)
            qv = *(const float4*)(Q + base + (size_t)(m0 + row) * HDIM + d);
        float4 w;
        w.x = to_tf32(qv.x * qscale); w.y = to_tf32(qv.y * qscale);
        w.z = to_tf32(qv.z * qscale); w.w = to_tf32(qv.w * qscale);
        *(float4*)&Ps[row * AST + d] = w;
    }
    __syncthreads();

    // ---- hoist Q fragments for both m-blocks into registers ----
    uint32_t qA[8][4], qB[8][4];
    {
        const uint32_t* pu = (const uint32_t*)Ps;
#pragma unroll
        for (int kt = 0; kt < 8; kt++) {
            qA[kt][0] = pu[rA * AST + kt * 8 + t];
            qA[kt][1] = pu[(rA + 8) * AST + kt * 8 + t];
            qA[kt][2] = pu[rA * AST + kt * 8 + t + 4];
            qA[kt][3] = pu[(rA + 8) * AST + kt * 8 + t + 4];
            qB[kt][0] = pu[rB * AST + kt * 8 + t];
            qB[kt][1] = pu[(rB + 8) * AST + kt * 8 + t];
            qB[kt][2] = pu[rB * AST + kt * 8 + t + 4];
            qB[kt][3] = pu[(rB + 8) * AST + kt * 8 + t + 4];
        }
    }

    float lA0 = 0.f, lA1 = 0.f, lB0 = 0.f, lB1 = 0.f;
    float oA[8][4], oB[8][4];
#pragma unroll
    for (int nt = 0; nt < 8; nt++)
#pragma unroll
        for (int j = 0; j < 4; j++) { oA[nt][j] = 0.f; oB[nt][j] = 0.f; }

    for (int kt0 = 0; kt0 < NTOK; kt0 += 64) {
        __syncthreads();
#pragma unroll
        for (int e = 0; e < 8; e++) {
            int idx = tid + e * 128;
            int row = idx >> 4;
            int d = (idx & 15) << 2;
            float4 kv = make_float4(0.f, 0.f, 0.f, 0.f);
            float4 vv = make_float4(0.f, 0.f, 0.f, 0.f);
            if (kt0 + row < NTOK) {
                kv = *(const float4*)(K + base + (size_t)(kt0 + row) * HDIM + d);
                vv = *(const float4*)(V + base + (size_t)(kt0 + row) * HDIM + d);
            }
            float4 kw, vw;
            kw.x = to_tf32(kv.x); kw.y = to_tf32(kv.y);
            kw.z = to_tf32(kv.z); kw.w = to_tf32(kv.w);
            vw.x = to_tf32(vv.x); vw.y = to_tf32(vv.y);
            vw.z = to_tf32(vv.z); vw.w = to_tf32(vv.w);
            *(float4*)&Ks[row * AST + d] = kw;
            *(float4*)&Vs[row * VST + d] = vw;
        }
        __syncthreads();

        // ---- S = (Q*qscale) K^T  (both m-blocks share B fragments) ----
        float sA[8][4], sB[8][4];
#pragma unroll
        for (int nt = 0; nt < 8; nt++)
#pragma unroll
            for (int j = 0; j < 4; j++) { sA[nt][j] = 0.f; sB[nt][j] = 0.f; }

        const uint32_t* ku = (const uint32_t*)Ks;
#pragma unroll
        for (int kt = 0; kt < 8; kt++) {
#pragma unroll
            for (int nt = 0; nt < 8; nt++) {
                uint32_t b0 = ku[(nt * 8 + g) * AST + kt * 8 + t];
                uint32_t b1 = ku[(nt * 8 + g) * AST + kt * 8 + t + 4];
                mma8(sA[nt], qA[kt][0], qA[kt][1], qA[kt][2], qA[kt][3], b0, b1);
                mma8(sB[nt], qB[kt][0], qB[kt][1], qB[kt][2], qB[kt][3], b0, b1);
            }
        }

        // ---- no-max softmax: p = 2^s ----
        bool tail = (kt0 + 64 > NTOK);
#pragma unroll
        for (int nt = 0; nt < 8; nt++) {
            if (tail) {
                int cg = kt0 + nt * 8 + 2 * t;
                if (cg >= NTOK) {
                    sA[nt][0] = -1e30f; sA[nt][2] = -1e30f;
                    sB[nt][0] = -1e30f; sB[nt][2] = -1e30f;
                }
                if (cg + 1 >= NTOK) {
                    sA[nt][1] = -1e30f; sA[nt][3] = -1e30f;
                    sB[nt][1] = -1e30f; sB[nt][3] = -1e30f;
                }
            }
            float pA0 = ex2(sA[nt][0]);
            float pA1 = ex2(sA[nt][1]);
            float pA2 = ex2(sA[nt][2]);
            float pA3 = ex2(sA[nt][3]);
            float pB0 = ex2(sB[nt][0]);
            float pB1 = ex2(sB[nt][1]);
            float pB2 = ex2(sB[nt][2]);
            float pB3 = ex2(sB[nt][3]);
            lA0 += pA0 + pA1; lA1 += pA2 + pA3;
            lB0 += pB0 + pB1; lB1 += pB2 + pB3;
            int col = nt * 8 + 2 * t;
            *(float2*)&Ps[rA * AST + col]       = make_float2(to_tf32(pA0), to_tf32(pA1));
            *(float2*)&Ps[(rA + 8) * AST + col] = make_float2(to_tf32(pA2), to_tf32(pA3));
            *(float2*)&Ps[rB * AST + col]       = make_float2(to_tf32(pB0), to_tf32(pB1));
            *(float2*)&Ps[(rB + 8) * AST + col] = make_float2(to_tf32(pB2), to_tf32(pB3));
        }
        __syncwarp();

        // ---- O += P V  (both m-blocks share B fragments) ----
        const uint32_t* pu = (const uint32_t*)Ps;
        const uint32_t* vu = (const uint32_t*)Vs;
#pragma unroll
        for (int kt = 0; kt < 8; kt++) {
            uint32_t aA0 = pu[rA * AST + kt * 8 + t];
            uint32_t aA1 = pu[(rA + 8) * AST + kt * 8 + t];
            uint32_t aA2 = pu[rA * AST + kt * 8 + t + 4];
            uint32_t aA3 = pu[(rA + 8) * AST + kt * 8 + t + 4];
            uint32_t aB0 = pu[rB * AST + kt * 8 + t];
            uint32_t aB1 = pu[(rB + 8) * AST + kt * 8 + t];
            uint32_t aB2 = pu[rB * AST + kt * 8 + t + 4];
            uint32_t aB3 = pu[(rB + 8) * AST + kt * 8 + t + 4];
#pragma unroll
            for (int nt = 0; nt < 8; nt++) {
                uint32_t b0 = vu[(kt * 8 + t) * VST + nt * 8 + g];
                uint32_t b1 = vu[(kt * 8 + t + 4) * VST + nt * 8 + g];
                mma8(oA[nt], aA0, aA1, aA2, aA3, b0, b1);
                mma8(oB[nt], aB0, aB1, aB2, aB3, b0, b1);
            }
        }
    }

    // deferred l reduction over the 4 t-lanes of each row group
    lA0 += __shfl_xor_sync(0xffffffffu, lA0, 1);
    lA0 += __shfl_xor_sync(0xffffffffu, lA0, 2);
    lA1 += __shfl_xor_sync(0xffffffffu, lA1, 1);
    lA1 += __shfl_xor_sync(0xffffffffu, lA1, 2);
    lB0 += __shfl_xor_sync(0xffffffffu, lB0, 1);
    lB0 += __shfl_xor_sync(0xffffffffu, lB0, 2);
    lB1 += __shfl_xor_sync(0xffffffffu, lB1, 1);
    lB1 += __shfl_xor_sync(0xffffffffu, lB1, 2);
    float iA0 = 1.f / lA0, iA1 = 1.f / lA1, iB0 = 1.f / lB0, iB1 = 1.f / lB1;
#pragma unroll
    for (int nt = 0; nt < 8; nt++) {
        int col = nt * 8 + 2 * t;
        int r;
        r = m0 + rA;
        if (r < NTOK)
            *(float2*)(O + base + (size_t)r * HDIM + col) =
                make_float2(oA[nt][0] * iA0, oA[nt][1] * iA0);
        r = m0 + rA + 8;
        if (r < NTOK)
            *(float2*)(O + base + (size_t)r * HDIM + col) =
                make_float2(oA[nt][2] * iA1, oA[nt][3] * iA1);
        r = m0 + rB;
        if (r < NTOK)
            *(float2*)(O + base + (size_t)r * HDIM + col) =
                make_float2(oB[nt][0] * iB0, oB[nt][1] * iB0);
        r = m0 + rB + 8;
        if (r < NTOK)
            *(float2*)(O + base + (size_t)r * HDIM + col) =
                make_float2(oB[nt][2] * iB1, oB[nt][3] * iB1);
    }
}

// ---------------- qkv projection GEMM (tf32 tensor-core) --------------------
#define GST 36

__global__ __launch_bounds__(128) void qkv_tc(const float* __restrict__ x,
                                              const float* __restrict__ W) {
    __shared__ float As[64 * GST];
    __shared__ float Bs[64 * GST];
    int tid = threadIdx.x;
    int warp = tid >> 5, lane = tid & 31;
    int g = lane >> 2, t = lane & 3;
    int m0 = blockIdx.x * 64;
    int o0 = blockIdx.y * 64;
    int b = blockIdx.z;
    const int r0 = warp * 16 + g;

    float c[8][4];
#pragma unroll
    for (int nt = 0; nt < 8; nt++)
#pragma unroll
        for (int j = 0; j < 4; j++) c[nt][j] = 0.f;

    for (int c0 = 0; c0 < CDIM; c0 += 32) {
        __syncthreads();
#pragma unroll
        for (int e = 0; e < 4; e++) {
            int idx = tid + e * 128;
            int row = idx >> 3;
            int cs = (idx & 7) << 2;
            float4 a4 = make_float4(0.f, 0.f, 0.f, 0.f);
            if (m0 + row < NTOK)
                a4 = *(const float4*)(x + (size_t)(m0 + row) * (BATCH * CDIM) + b * CDIM + c0 + cs);
            float4 aw;
            aw.x = to_tf32(a4.x); aw.y = to_tf32(a4.y);
            aw.z = to_tf32(a4.z); aw.w = to_tf32(a4.w);
            *(float4*)&As[row * GST + cs] = aw;
            float4 b4 = *(const float4*)(W + (size_t)(o0 + row) * CDIM + c0 + cs);
            float4 bw;
            bw.x = to_tf32(b4.x); bw.y = to_tf32(b4.y);
            bw.z = to_tf32(b4.z); bw.w = to_tf32(b4.w);
            *(float4*)&Bs[row * GST + cs] = bw;
        }
        __syncthreads();

        const uint32_t* au = (const uint32_t*)As;
        const uint32_t* bu = (const uint32_t*)Bs;
#pragma unroll
        for (int kt = 0; kt < 4; kt++) {
            uint32_t a0 = au[r0 * GST + kt * 8 + t];
            uint32_t a1 = au[(r0 + 8) * GST + kt * 8 + t];
            uint32_t a2 = au[r0 * GST + kt * 8 + t + 4];
            uint32_t a3 = au[(r0 + 8) * GST + kt * 8 + t + 4];
#pragma unroll
            for (int nt = 0; nt < 8; nt++) {
                uint32_t b0 = bu[(nt * 8 + g) * GST + kt * 8 + t];
                uint32_t b1 = bu[(nt * 8 + g) * GST + kt * 8 + t + 4];
                mma8(c[nt], a0, a1, a2, a3, b0, b1);
            }
        }
    }

    int tsel = o0 / CDIM;
    int h = (o0 % CDIM) >> 6;
    float* dst = (tsel == 0) ? g_q : ((tsel == 1) ? g_k : g_v);
    dst += (size_t)((b * NHEAD + h) * NTOK) * HDIM;
    int gr0 = m0 + r0, gr1 = m0 + r0 + 8;
#pragma unroll
    for (int nt = 0; nt < 8; nt++) {
        int col = nt * 8 + 2 * t;
        if (gr0 < NTOK)
            *(float2*)&dst[(size_t)gr0 * HDIM + col] = make_float2(c[nt][0], c[nt][1]);
        if (gr1 < NTOK)
            *(float2*)&dst[(size_t)gr1 * HDIM + col] = make_float2(c[nt][2], c[nt][3]);
    }
}

// ---------------- output projection GEMM (tf32 tensor-core) -----------------
__global__ __launch_bounds__(128) void proj_tc(const float* __restrict__ src,
                                               const float* __restrict__ W,
                                               const float* __restrict__ bias,
                                               float* __restrict__ out,
                                               float prescale) {
    __shared__ float As[64 * GST];
    __shared__ float Bs[64 * GST];
    int tid = threadIdx.x;
    int warp = tid >> 5, lane = tid & 31;
    int g = lane >> 2, t = lane & 3;
    int m0 = blockIdx.x * 64;
    int o0 = blockIdx.y * 64;
    int b = blockIdx.z;
    const int r0 = warp * 16 + g;

    float c[8][4];
#pragma unroll
    for (int nt = 0; nt < 8; nt++)
#pragma unroll
        for (int j = 0; j < 4; j++) c[nt][j] = 0.f;

    for (int c0 = 0; c0 < CDIM; c0 += 32) {
        int h = c0 >> 6;
        int dlo = c0 & 63;
        __syncthreads();
#pragma unroll
        for (int e = 0; e < 4; e++) {
            int idx = tid + e * 128;
            int row = idx >> 3;
            int cs = (idx & 7) << 2;
            float4 a4 = make_float4(0.f, 0.f, 0.f, 0.f);
            if (m0 + row < NTOK)
                a4 = *(const float4*)(src + (size_t)((b * NHEAD + h) * NTOK + m0 + row) * HDIM + dlo + cs);
            float4 aw;
            aw.x = to_tf32(a4.x); aw.y = to_tf32(a4.y);
            aw.z = to_tf32(a4.z); aw.w = to_tf32(a4.w);
            *(float4*)&As[row * GST + cs] = aw;
            float4 b4 = *(const float4*)(W + (size_t)(o0 + row) * CDIM + c0 + cs);
            float4 bw;
            bw.x = to_tf32(b4.x); bw.y = to_tf32(b4.y);
            bw.z = to_tf32(b4.z); bw.w = to_tf32(b4.w);
            *(float4*)&Bs[row * GST + cs] = bw;
        }
        __syncthreads();

        const uint32_t* au = (const uint32_t*)As;
        const uint32_t* bu = (const uint32_t*)Bs;
#pragma unroll
        for (int kt = 0; kt < 4; kt++) {
            uint32_t a0 = au[r0 * GST + kt * 8 + t];
            uint32_t a1 = au[(r0 + 8) * GST + kt * 8 + t];
            uint32_t a2 = au[r0 * GST + kt * 8 + t + 4];
            uint32_t a3 = au[(r0 + 8) * GST + kt * 8 + t + 4];
#pragma unroll
            for (int nt = 0; nt < 8; nt++) {
                uint32_t b0 = bu[(nt * 8 + g) * GST + kt * 8 + t];
                uint32_t b1 = bu[(nt * 8 + g) * GST + kt * 8 + t + 4];
                mma8(c[nt], a0, a1, a2, a3, b0, b1);
            }
        }
    }

    int gr0 = m0 + r0, gr1 = m0 + r0 + 8;
#pragma unroll
    for (int nt = 0; nt < 8; nt++) {
        int col = nt * 8 + 2 * t;
        float b0 = bias[o0 + col], b1 = bias[o0 + col + 1];
        if (gr0 < NTOK)
            *(float2*)(out + (size_t)gr0 * (BATCH * CDIM) + b * CDIM + o0 + col) =
                make_float2(c[nt][0] * prescale + b0, c[nt][1] * prescale + b1);
        if (gr1 < NTOK)
            *(float2*)(out + (size_t)gr1 * (BATCH * CDIM) + b * CDIM + o0 + col) =
                make_float2(c[nt][2] * prescale + b0, c[nt][3] * prescale + b1);
    }
}

// ---------------- host orchestration ---------------------------------------
extern "C" void kernel_launch(void* const* d_in, const int* in_sizes, int n_in,
                              void* d_out, int out_size) {
    const float* x = (const float*)d_in[0];
    const float* Wqkv = (const float*)d_in[1];
    const float* Wproj = (const float*)d_in[2];
    const float* bproj = (const float*)d_in[3];
    float* out = (float*)d_out;

    cudaFuncSetAttribute(attn_tc, cudaFuncAttributeMaxDynamicSharedMemorySize,
                         ATT_SMEM);

    float *q, *k, *v, *xs, *t1, *accb;
    cudaGetSymbolAddress((void**)&q, g_q);
    cudaGetSymbolAddress((void**)&k, g_k);
    cudaGetSymbolAddress((void**)&v, g_v);
    cudaGetSymbolAddress((void**)&xs, g_xs);
    cudaGetSymbolAddress((void**)&t1, g_t1);
    cudaGetSymbolAddress((void**)&accb, g_acc);

    const int LN_GRID = (BH * NTOK * 32 + 255) / 256;
    const int ADD_GRID = (BHND / 4 + 255) / 256;
    dim3 ga((NTOK + 127) / 128, BH);       // 13 x 96
    dim3 gq((NTOK + 63) / 64, 36, BATCH);
    dim3 gp((NTOK + 63) / 64, 12, BATCH);

    rownorm_kernel<<<(BATCH * NTOK * 32 + 255) / 256, 256>>>(x);
    invtemp_kernel<<<BATCH, 256>>>();

    qkv_tc<<<gq, 128>>>(x, Wqkv);

    // original attention -> x_ori (second half of output)
    attn_tc<<<ga, 128, ATT_SMEM>>>(q, k, v, t1, 0, 0.125f);
    proj_tc<<<gp, 128>>>(t1, Wproj, bproj, out + NBC, 1.0f);

    // branch(v)
    l2norm_kernel<<<LN_GRID, 256>>>(v, xs);
    attn_tc<<<ga, 128, ATT_SMEM>>>(xs, xs, xs, t1, 1, 0.f);
    l2norm_kernel<<<LN_GRID, 256>>>(t1, xs);
    attn_tc<<<ga, 128, ATT_SMEM>>>(xs, xs, v, accb, 1, 0.f);

    // branch(k)
    l2norm_kernel<<<LN_GRID, 256>>>(k, xs);
    attn_tc<<<ga, 128, ATT_SMEM>>>(xs, xs, xs, t1, 1, 0.f);
    l2norm_kernel<<<LN_GRID, 256>>>(t1, xs);
    attn_tc<<<ga, 128, ATT_SMEM>>>(xs, xs, v, t1, 1, 0.f);
    add_kernel<<<ADD_GRID, 256>>>(accb, t1);

    // branch(q)
    l2norm_kernel<<<LN_GRID, 256>>>(q, xs);
    attn_tc<<<ga, 128, ATT_SMEM>>>(xs, xs, xs, t1, 1, 0.f);
    l2norm_kernel<<<LN_GRID, 256>>>(t1, xs);
    attn_tc<<<ga, 128, ATT_SMEM>>>(xs, xs, v, t1, 1, 0.f);
    add_kernel<<<ADD_GRID, 256>>>(accb, t1);

    proj_tc<<<gp, 128>>>(accb, Wproj, bproj, out, 1.0f / 3.0f);
}